// round 16
// baseline (speedup 1.0000x reference)
#include <cuda_runtime.h>
#include <cuda_fp16.h>
#include <math.h>
#include <stdint.h>

#define BB 16
#define LQ 2048
#define LC 2048
#define DD 1024
#define NQ_ELEMS  (BB * LQ * DD)
#define NB_ELEMS  (BB * LC * DD)
#define NW_ELEMS  (DD * DD)
#define NA_ELEMS  ((long long)BB * LQ * LC)

// scratch (single fp16)
__device__ __half g_qh[NQ_ELEMS];
__device__ __half g_bh[NB_ELEMS];
__device__ __half g_qwh[NQ_ELEMS];
__device__ __half g_eh[NA_ELEMS];
__device__ __half g_vh[NQ_ELEMS];
__device__ __half g_wch[NW_ELEMS];
__device__ __half g_woqh[NW_ELEMS];
__device__ __half g_woch[NW_ELEMS];
__device__ float  g_rowinv[BB * LQ];

// ---- helpers ----
__device__ __forceinline__ uint32_t smem_u32(const void* p) {
    uint32_t a;
    asm("{ .reg .u64 t; cvta.to.shared.u64 t, %1; cvt.u32.u64 %0, t; }" : "=r"(a) : "l"(p));
    return a;
}
__device__ __forceinline__ void cp16(uint32_t dst, const void* src) {
    asm volatile("cp.async.cg.shared.global [%0], [%1], 16;" :: "r"(dst), "l"(src) : "memory");
}
__device__ __forceinline__ void cp_commit() { asm volatile("cp.async.commit_group;" ::: "memory"); }
template <int N> __device__ __forceinline__ void cp_wait() {
    asm volatile("cp.async.wait_group %0;" :: "n"(N) : "memory");
}
__device__ __forceinline__ void ldm4(uint32_t* r, uint32_t addr) {
    asm volatile("ldmatrix.sync.aligned.m8n8.x4.shared.b16 {%0,%1,%2,%3}, [%4];"
                 : "=r"(r[0]), "=r"(r[1]), "=r"(r[2]), "=r"(r[3]) : "r"(addr));
}
__device__ __forceinline__ void ldm4t(uint32_t* r, uint32_t addr) {
    asm volatile("ldmatrix.sync.aligned.m8n8.x4.trans.shared.b16 {%0,%1,%2,%3}, [%4];"
                 : "=r"(r[0]), "=r"(r[1]), "=r"(r[2]), "=r"(r[3]) : "r"(addr));
}
__device__ __forceinline__ void mma16816(float* c, const uint32_t* a, const uint32_t* b) {
    asm volatile("mma.sync.aligned.m16n8k16.row.col.f32.f16.f16.f32 "
                 "{%0,%1,%2,%3},{%4,%5,%6,%7},{%8,%9},{%0,%1,%2,%3};"
                 : "+f"(c[0]), "+f"(c[1]), "+f"(c[2]), "+f"(c[3])
                 : "r"(a[0]), "r"(a[1]), "r"(a[2]), "r"(a[3]), "r"(b[0]), "r"(b[1]));
}

// ---- HMMA GEMM (128x256 tile, BK=128, 2-stage) ----
// BNN=0: C = alpha * sum_seg A_s @ B_s^T   (B_s: [N,K] row-major, ld=ldB)
// BNN=1: C = alpha * A @ B                  (B: [K,N] row-major, ld=ldB)
// MODE 0: fp32 out; 2: fp16 out; 3: fp16 exp(alpha*v) out; 4: fp16 (v*rowscale) out
#define BM 128
#define BN 256
#define BK 128
#define STRD 136                    // K-major rows: 128 + 8 pad (halfwords)
#define STRDN 264                   // NN B rows: 256 + 8 pad (halfwords)
#define SA_BYTES (BM * STRD * 2)    // 34816
#define SB_BYTES (BN * STRD * 2)    // 69632 >= 128*264*2 = 67584
#define STAGE_BYTES (SA_BYTES + SB_BYTES)
#define NSTAGE 2
#define SMEM_DYN (NSTAGE * STAGE_BYTES)   // 208,896

struct GemmArgs {
    const __half *a0, *b0, *a1, *b1;
};

template <int MODE, int BNN>
__global__ void __launch_bounds__(256)
hgemm(GemmArgs seg, int nseg, int K, int ldB,
      float* __restrict__ Cf, __half* __restrict__ Ch,
      const float* __restrict__ rowscale,
      int ldc, long long sA, long long sB, long long sC, float alpha)
{
    extern __shared__ char dynsmem[];
    const uint32_t base0 = smem_u32(dynsmem);

    const int tid = threadIdx.x, lane = tid & 31, wid = tid >> 5;
    const int warp_m = wid & 1, warp_n = wid >> 1;   // 2x4 warps -> 64x64 per warp
    const int bm = blockIdx.y, bn = blockIdx.x, bz = blockIdx.z;

    const __half* Aseg[2] = { seg.a0, seg.a1 };
    const __half* Bseg[2] = { seg.b0, seg.b1 };

    const int tps = K / BK;
    const int CT = nseg * tps;

    float acc[4][8][4];
#pragma unroll
    for (int i = 0; i < 4; i++)
#pragma unroll
        for (int j = 0; j < 8; j++)
#pragma unroll
            for (int q = 0; q < 4; q++) acc[i][j][q] = 0.0f;

    // chunk = 16B = 8 hw. A/NT-B rows have 16 chunks; NN-B rows have 32 chunks.
    const int krow = tid >> 4, koff = (tid & 15) * 8;    // 16 rows/pass (K-major)
    const int nrow = tid >> 5, noff = (tid & 31) * 8;    // NN B: 8 rows/pass

    auto load_tile = [&](int t, int buf) {
        const int s = t / tps, kk = (t - s * tps) * BK;
        const __half* Ab = Aseg[s] + bz * sA + (long long)(bm * BM) * K + kk;
        const uint32_t sa = base0 + buf * STAGE_BYTES;
        const uint32_t sb = sa + SA_BYTES;
#pragma unroll
        for (int i = 0; i < 8; i++) {            // A: 128 rows
            const int row = krow + i * 16;
            cp16(sa + (uint32_t)(row * STRD + koff) * 2, Ab + (long long)row * K + koff);
        }
        if (BNN == 0) {
            const __half* Bb = Bseg[s] + bz * sB + (long long)(bn * BN) * ldB + kk;
#pragma unroll
            for (int i = 0; i < 16; i++) {       // B: 256 rows
                const int row = krow + i * 16;
                cp16(sb + (uint32_t)(row * STRD + koff) * 2, Bb + (long long)row * ldB + koff);
            }
        } else {
            const __half* Bb = Bseg[s] + bz * sB + (long long)kk * ldB + bn * BN;
#pragma unroll
            for (int i = 0; i < 16; i++) {       // B: 128 rows x 32 chunks
                const int row = nrow + i * 8;
                cp16(sb + (uint32_t)(row * STRDN + noff) * 2, Bb + (long long)row * ldB + noff);
            }
        }
        cp_commit();
    };

    const uint32_t a_base = (uint32_t)(((warp_m * 64 + (lane & 15)) * STRD + (lane >> 4) * 8) * 2);
    uint32_t b_base[4];
#pragma unroll
    for (int nf = 0; nf < 4; nf++) {
        if (BNN == 0)
            b_base[nf] = (uint32_t)(((warp_n * 64 + nf * 16 + ((lane >> 4) << 3) + (lane & 7)) * STRD
                                     + ((lane >> 3) & 1) * 8) * 2);
        else
            b_base[nf] = (uint32_t)(((lane & 15) * STRDN
                                     + warp_n * 64 + nf * 16 + (lane >> 4) * 8) * 2);
    }

    // register fragment double buffers
    uint32_t afr[2][4][4], bfr[2][8][2];
    auto ldfrag = [&](int buf, uint32_t sa, int kk) {
        const uint32_t sb = sa + SA_BYTES;
        const uint32_t kaddA = (uint32_t)kk * 32;
#pragma unroll
        for (int im = 0; im < 4; im++)
            ldm4(afr[buf][im], sa + a_base + (uint32_t)(im * 16 * STRD * 2) + kaddA);
        const uint32_t kaddB = (BNN == 0) ? (uint32_t)kk * 32 : (uint32_t)kk * 16 * STRDN * 2;
#pragma unroll
        for (int nf = 0; nf < 4; nf++) {
            uint32_t r[4];
            if (BNN == 0) ldm4(r, sb + b_base[nf] + kaddB);
            else          ldm4t(r, sb + b_base[nf] + kaddB);
            bfr[buf][2 * nf][0] = r[0];     bfr[buf][2 * nf][1] = r[1];
            bfr[buf][2 * nf + 1][0] = r[2]; bfr[buf][2 * nf + 1][1] = r[3];
        }
    };

    load_tile(0, 0);
    cp_wait<0>();
    __syncthreads();

    int cur = 0;
    ldfrag(0, base0, 0);

    for (int t = 0; t < CT; ++t) {
        const uint32_t sa_t = base0 + (t & 1) * STAGE_BYTES;
        if (t + 1 < CT) load_tile(t + 1, (t + 1) & 1);

#pragma unroll
        for (int kk = 0; kk < 8; kk++) {
            if (kk < 7) ldfrag(cur ^ 1, sa_t, kk + 1);
#pragma unroll
            for (int im = 0; im < 4; im++)
#pragma unroll
                for (int in = 0; in < 8; in++)
                    mma16816(acc[im][in], afr[cur][im], bfr[cur][in]);
            cur ^= 1;
        }

        cp_wait<0>();
        __syncthreads();
        if (t + 1 < CT)
            ldfrag(cur, base0 + ((t + 1) & 1) * STAGE_BYTES, 0);
    }

    // epilogue
    const int gr = lane >> 2, qd = lane & 3;
    float rs[4][2];
    if (MODE == 4) {
#pragma unroll
        for (int im = 0; im < 4; im++)
#pragma unroll
            for (int h = 0; h < 2; h++)
                rs[im][h] = rowscale[bz * LQ + bm * BM + warp_m * 64 + im * 16 + gr + h * 8];
    }
#pragma unroll
    for (int im = 0; im < 4; im++) {
#pragma unroll
        for (int in = 0; in < 8; in++) {
            const long long row0 = (long long)bm * BM + warp_m * 64 + im * 16 + gr;
            const int col = bn * BN + warp_n * 64 + in * 8 + qd * 2;
#pragma unroll
            for (int h = 0; h < 2; h++) {
                const long long row = row0 + h * 8;
                const float v0 = acc[im][in][2 * h + 0];
                const float v1 = acc[im][in][2 * h + 1];
                if (MODE == 0) {
                    *(float2*)(Cf + bz * sC + row * ldc + col) = make_float2(alpha * v0, alpha * v1);
                } else if (MODE == 2) {
                    *(__half2*)(Ch + bz * sC + row * ldc + col) =
                        __halves2half2(__float2half_rn(alpha * v0), __float2half_rn(alpha * v1));
                } else if (MODE == 3) {
                    *(__half2*)(Ch + bz * sC + row * ldc + col) =
                        __halves2half2(__float2half_rn(__expf(alpha * v0)),
                                       __float2half_rn(__expf(alpha * v1)));
                } else {  // MODE 4
                    const float s = rs[im][h];
                    *(__half2*)(Ch + bz * sC + row * ldc + col) =
                        __halves2half2(__float2half_rn(s * v0), __float2half_rn(s * v1));
                }
            }
        }
    }
}

// ---- fp32 -> fp16 convert (two arrays in one launch) ----
__global__ void __launch_bounds__(256)
conv2_f16(const float4* __restrict__ s0, __half2* __restrict__ d0, int n0,
          const float4* __restrict__ s1, __half2* __restrict__ d1, int n1)
{
    const int total = n0 + n1;
    for (int i = blockIdx.x * blockDim.x + threadIdx.x; i < total; i += gridDim.x * blockDim.x) {
        const float4* s = (i < n0) ? s0 : s1;
        __half2* d = (i < n0) ? d0 : d1;
        const int j = (i < n0) ? i : i - n0;
        const float4 v = s[j];
        d[2 * j]     = __halves2half2(__float2half_rn(v.x), __float2half_rn(v.y));
        d[2 * j + 1] = __halves2half2(__float2half_rn(v.z), __float2half_rn(v.w));
    }
}

__global__ void __launch_bounds__(256)
conv3_f16(const float4* __restrict__ s0, __half2* __restrict__ d0,
          const float4* __restrict__ s1, __half2* __restrict__ d1,
          const float4* __restrict__ s2, __half2* __restrict__ d2, int n)
{
    for (int i = blockIdx.x * blockDim.x + threadIdx.x; i < 3 * n; i += gridDim.x * blockDim.x) {
        const int sel = i / n, j = i - sel * n;
        const float4* s = (sel == 0) ? s0 : (sel == 1) ? s1 : s2;
        __half2* d = (sel == 0) ? d0 : (sel == 1) ? d1 : d2;
        const float4 v = s[j];
        d[2 * j]     = __halves2half2(__float2half_rn(v.x), __float2half_rn(v.y));
        d[2 * j + 1] = __halves2half2(__float2half_rn(v.z), __float2half_rn(v.w));
    }
}

// ---- sum rows of E (fp16), emit attn fp32 = E*inv and rowinv ----
__global__ void __launch_bounds__(256)
sumscale(const __half* __restrict__ E, float* __restrict__ attn, float* __restrict__ rowinv)
{
    const long long row = blockIdx.x;
    const __half* pe = E + row * (long long)LC;
    float* pa = attn + row * (long long)LC;
    const int tid = threadIdx.x;
    const int lane = tid & 31, wid = tid >> 5;
    __shared__ float sred[8];
    __shared__ float sbcast;

    const uint4 v = ((const uint4*)pe)[tid];   // 8 halfs
    float f[8];
    {
        const __half2* hp = (const __half2*)&v;
#pragma unroll
        for (int i = 0; i < 4; i++) {
            const float2 t = __half22float2(hp[i]);
            f[2 * i] = t.x; f[2 * i + 1] = t.y;
        }
    }

    float ssum = 0.0f;
#pragma unroll
    for (int i = 0; i < 8; i++) ssum += f[i];
#pragma unroll
    for (int off = 16; off; off >>= 1) ssum += __shfl_xor_sync(0xffffffffu, ssum, off);
    if (lane == 0) sred[wid] = ssum;
    __syncthreads();
    if (tid == 0) {
        float t = 0.0f;
#pragma unroll
        for (int w = 0; w < 8; w++) t += sred[w];
        sbcast = 1.0f / t;
        rowinv[row] = sbcast;
    }
    __syncthreads();
    const float inv = sbcast;

    ((float4*)pa)[2 * tid]     = make_float4(f[0] * inv, f[1] * inv, f[2] * inv, f[3] * inv);
    ((float4*)pa)[2 * tid + 1] = make_float4(f[4] * inv, f[5] * inv, f[6] * inv, f[7] * inv);
}

static void* dsym(const void* sym) { void* p = nullptr; cudaGetSymbolAddress(&p, sym); return p; }

extern "C" void kernel_launch(void* const* d_in, const int* in_sizes, int n_in,
                              void* d_out, int out_size)
{
    const float* query = (const float*)d_in[0];
    const float* bank  = (const float*)d_in[1];
    const float* Wc    = (const float*)d_in[2];
    const float* Woq   = (const float*)d_in[3];
    const float* Woc   = (const float*)d_in[4];

    float* out  = (float*)d_out;
    float* attn = out + (long long)BB * LQ * DD;

    __half* qh   = (__half*)dsym(g_qh);
    __half* bh   = (__half*)dsym(g_bh);
    __half* qwh  = (__half*)dsym(g_qwh);
    __half* eh   = (__half*)dsym(g_eh);
    __half* vh   = (__half*)dsym(g_vh);
    __half* wch  = (__half*)dsym(g_wch);
    __half* woqh = (__half*)dsym(g_woqh);
    __half* woch = (__half*)dsym(g_woch);
    float*  rinv = (float*)dsym(g_rowinv);

    cudaFuncSetAttribute(hgemm<0,0>, cudaFuncAttributeMaxDynamicSharedMemorySize, SMEM_DYN);
    cudaFuncSetAttribute(hgemm<2,1>, cudaFuncAttributeMaxDynamicSharedMemorySize, SMEM_DYN);
    cudaFuncSetAttribute(hgemm<3,0>, cudaFuncAttributeMaxDynamicSharedMemorySize, SMEM_DYN);
    cudaFuncSetAttribute(hgemm<4,1>, cudaFuncAttributeMaxDynamicSharedMemorySize, SMEM_DYN);

    conv2_f16<<<8192, 256>>>((const float4*)query, (__half2*)qh, NQ_ELEMS / 4,
                             (const float4*)bank,  (__half2*)bh, NB_ELEMS / 4);
    conv3_f16<<<1536, 256>>>((const float4*)Wc,  (__half2*)wch,
                             (const float4*)Woq, (__half2*)woqh,
                             (const float4*)Woc, (__half2*)woch, NW_ELEMS / 4);

    // G1': qW = q @ Wc (NN, flat M=32768) -> fp16 qwh
    {
        GemmArgs s = { qh, wch, nullptr, nullptr };
        hgemm<2,1><<<dim3(DD / BN, (BB * LQ) / BM, 1), 256, SMEM_DYN>>>(
            s, 1, DD, DD, nullptr, qwh, nullptr, DD, 0LL, 0LL, 0LL, 1.0f);
    }
    // G2': E = exp((1/32) qW @ bank^T) (NT, per batch) -> fp16 eh
    {
        GemmArgs s = { qwh, bh, nullptr, nullptr };
        hgemm<3,0><<<dim3(LC / BN, LQ / BM, BB), 256, SMEM_DYN>>>(
            s, 1, DD, DD, nullptr, eh, nullptr, LC,
            (long long)LQ * DD, (long long)LC * DD, (long long)LQ * LC, 0.03125f);
    }
    // sums + attn fp32 output + rowinv
    sumscale<<<BB * LQ, 256>>>(eh, attn, rinv);

    // G3: context = (E @ bank) * rowinv (NN, per batch) -> fp16 vh
    {
        GemmArgs s = { eh, bh, nullptr, nullptr };
        hgemm<4,1><<<dim3(DD / BN, LQ / BM, BB), 256, SMEM_DYN>>>(
            s, 1, LC, DD, nullptr, vh, rinv, DD,
            (long long)LQ * LC, (long long)LC * DD, (long long)LQ * DD, 1.0f);
    }
    // G4: out = context @ Woc^T + q @ Woq^T (flat M=32768, 2 segs) -> fp32
    {
        GemmArgs s = { vh, woch, qh, woqh };
        hgemm<0,0><<<dim3(DD / BN, (BB * LQ) / BM, 1), 256, SMEM_DYN>>>(
            s, 2, DD, DD, out, nullptr, nullptr, DD, 0LL, 0LL, 0LL, 1.0f);
    }
}

// round 17
// speedup vs baseline: 1.7341x; 1.7341x over previous
#include <cuda_runtime.h>
#include <cuda_fp16.h>
#include <math.h>
#include <stdint.h>

#define BB 16
#define LQ 2048
#define LC 2048
#define DD 1024
#define NQ_ELEMS  (BB * LQ * DD)
#define NB_ELEMS  (BB * LC * DD)
#define NW_ELEMS  (DD * DD)
#define NA_ELEMS  ((long long)BB * LQ * LC)

// scratch (single fp16)
__device__ __half g_qh[NQ_ELEMS];
__device__ __half g_bh[NB_ELEMS];
__device__ __half g_qwh[NQ_ELEMS];
__device__ __half g_eh[NA_ELEMS];
__device__ __half g_vh[NQ_ELEMS];
__device__ __half g_wctT[NW_ELEMS];   // Wc^T  [d, e] fp16
__device__ __half g_woqh[NW_ELEMS];
__device__ __half g_woch[NW_ELEMS];
__device__ float  g_rowinv[BB * LQ];

// ---- helpers ----
__device__ __forceinline__ uint32_t smem_u32(const void* p) {
    uint32_t a;
    asm("{ .reg .u64 t; cvta.to.shared.u64 t, %1; cvt.u32.u64 %0, t; }" : "=r"(a) : "l"(p));
    return a;
}
__device__ __forceinline__ void cp16(uint32_t dst, const void* src) {
    asm volatile("cp.async.cg.shared.global [%0], [%1], 16;" :: "r"(dst), "l"(src) : "memory");
}
__device__ __forceinline__ void cp_commit() { asm volatile("cp.async.commit_group;" ::: "memory"); }
template <int N> __device__ __forceinline__ void cp_wait() {
    asm volatile("cp.async.wait_group %0;" :: "n"(N) : "memory");
}
__device__ __forceinline__ void ldm4(uint32_t* r, uint32_t addr) {
    asm volatile("ldmatrix.sync.aligned.m8n8.x4.shared.b16 {%0,%1,%2,%3}, [%4];"
                 : "=r"(r[0]), "=r"(r[1]), "=r"(r[2]), "=r"(r[3]) : "r"(addr));
}
__device__ __forceinline__ void ldm4t(uint32_t* r, uint32_t addr) {
    asm volatile("ldmatrix.sync.aligned.m8n8.x4.trans.shared.b16 {%0,%1,%2,%3}, [%4];"
                 : "=r"(r[0]), "=r"(r[1]), "=r"(r[2]), "=r"(r[3]) : "r"(addr));
}
__device__ __forceinline__ void mma16816(float* c, const uint32_t* a, const uint32_t* b) {
    asm volatile("mma.sync.aligned.m16n8k16.row.col.f32.f16.f16.f32 "
                 "{%0,%1,%2,%3},{%4,%5,%6,%7},{%8,%9},{%0,%1,%2,%3};"
                 : "+f"(c[0]), "+f"(c[1]), "+f"(c[2]), "+f"(c[3])
                 : "r"(a[0]), "r"(a[1]), "r"(a[2]), "r"(a[3]), "r"(b[0]), "r"(b[1]));
}

// ---- HMMA GEMM (R9 engine: 128x256, BK=64, NSTAGE=3, 256 thr, reg frag double-buffer) ----
// BNN=0: C = alpha * sum_seg A_s @ B_s^T   (B_s: [N,K] row-major, ld=ldB)
// BNN=1: C = alpha * A @ B                  (B: [K,N] row-major, ld=ldB)
// MODE 0: fp32 out; 2: fp16 out; 3: fp16 exp(alpha*v) out; 4: fp16 (v*rowscale) out
#define BM 128
#define BN 256
#define BK 64
#define STRD 72
#define STRDN 264
#define SA_BYTES (BM * STRD * 2)
#define SB_BYTES (BN * STRD * 2)
#define STAGE_BYTES (SA_BYTES + SB_BYTES)
#define NSTAGE 3
#define SMEM_DYN (NSTAGE * STAGE_BYTES)

struct GemmArgs {
    const __half *a0, *b0, *a1, *b1;
};

template <int MODE, int BNN>
__global__ void __launch_bounds__(256)
hgemm(GemmArgs seg, int nseg, int K, int ldB,
      float* __restrict__ Cf, __half* __restrict__ Ch,
      const float* __restrict__ rowscale,
      int ldc, long long sA, long long sB, long long sC, float alpha)
{
    extern __shared__ char dynsmem[];
    const uint32_t base0 = smem_u32(dynsmem);

    const int tid = threadIdx.x, lane = tid & 31, wid = tid >> 5;
    const int warp_m = wid & 1, warp_n = wid >> 1;   // 2x4 warps -> 64x64 per warp
    const int bm = blockIdx.y, bn = blockIdx.x, bz = blockIdx.z;

    const __half* Aseg[2] = { seg.a0, seg.a1 };
    const __half* Bseg[2] = { seg.b0, seg.b1 };

    const int tps = K / BK;
    const int CT = nseg * tps;

    float acc[4][8][4];
#pragma unroll
    for (int i = 0; i < 4; i++)
#pragma unroll
        for (int j = 0; j < 8; j++)
#pragma unroll
            for (int q = 0; q < 4; q++) acc[i][j][q] = 0.0f;

    const int lrow = tid >> 3, loff = (tid & 7) * 8;
    const int nrow = tid >> 5, noff = (tid & 31) * 8;

    auto load_tile = [&](int t, int buf) {
        const int s = t / tps, kk = (t - s * tps) * BK;
        const __half* Ab = Aseg[s] + bz * sA + (long long)(bm * BM) * K + kk;
        const uint32_t sa = base0 + buf * STAGE_BYTES;
        const uint32_t sb = sa + SA_BYTES;
#pragma unroll
        for (int i = 0; i < 4; i++) {
            const int row = lrow + i * 32;
            cp16(sa + (uint32_t)(row * STRD + loff) * 2, Ab + (long long)row * K + loff);
        }
        if (BNN == 0) {
            const __half* Bb = Bseg[s] + bz * sB + (long long)(bn * BN) * ldB + kk;
#pragma unroll
            for (int i = 0; i < 8; i++) {
                const int row = lrow + i * 32;
                cp16(sb + (uint32_t)(row * STRD + loff) * 2, Bb + (long long)row * ldB + loff);
            }
        } else {
            const __half* Bb = Bseg[s] + bz * sB + (long long)kk * ldB + bn * BN;
#pragma unroll
            for (int i = 0; i < 8; i++) {
                const int row = nrow + i * 8;
                cp16(sb + (uint32_t)(row * STRDN + noff) * 2, Bb + (long long)row * ldB + noff);
            }
        }
        cp_commit();
    };

    const uint32_t a_base = (uint32_t)(((warp_m * 64 + (lane & 15)) * STRD + (lane >> 4) * 8) * 2);
    uint32_t b_base[4];
#pragma unroll
    for (int nf = 0; nf < 4; nf++) {
        if (BNN == 0)
            b_base[nf] = (uint32_t)(((warp_n * 64 + nf * 16 + ((lane >> 4) << 3) + (lane & 7)) * STRD
                                     + ((lane >> 3) & 1) * 8) * 2);
        else
            b_base[nf] = (uint32_t)(((lane & 15) * STRDN
                                     + warp_n * 64 + nf * 16 + (lane >> 4) * 8) * 2);
    }

    // register fragment double buffers
    uint32_t afr[2][4][4], bfr[2][8][2];
    auto ldfrag = [&](int buf, uint32_t sa, int kk) {
        const uint32_t sb = sa + SA_BYTES;
        const uint32_t kaddA = (uint32_t)kk * 32;
#pragma unroll
        for (int im = 0; im < 4; im++)
            ldm4(afr[buf][im], sa + a_base + (uint32_t)(im * 16 * STRD * 2) + kaddA);
        const uint32_t kaddB = (BNN == 0) ? (uint32_t)kk * 32 : (uint32_t)kk * 16 * STRDN * 2;
#pragma unroll
        for (int nf = 0; nf < 4; nf++) {
            uint32_t r[4];
            if (BNN == 0) ldm4(r, sb + b_base[nf] + kaddB);
            else          ldm4t(r, sb + b_base[nf] + kaddB);
            bfr[buf][2 * nf][0] = r[0];     bfr[buf][2 * nf][1] = r[1];
            bfr[buf][2 * nf + 1][0] = r[2]; bfr[buf][2 * nf + 1][1] = r[3];
        }
    };

    load_tile(0, 0);
    if (CT > 1) load_tile(1, 1); else cp_commit();
    cp_wait<1>();
    __syncthreads();

    int cur = 0;
    ldfrag(0, base0, 0);

    for (int t = 0; t < CT; ++t) {
        const uint32_t sa_t = base0 + (t % NSTAGE) * STAGE_BYTES;
        if (t + 2 < CT) load_tile(t + 2, (t + 2) % NSTAGE); else cp_commit();

#pragma unroll
        for (int kk = 0; kk < 4; kk++) {
            if (kk < 3) ldfrag(cur ^ 1, sa_t, kk + 1);
#pragma unroll
            for (int im = 0; im < 4; im++)
#pragma unroll
                for (int in = 0; in < 8; in++)
                    mma16816(acc[im][in], afr[cur][im], bfr[cur][in]);
            cur ^= 1;
        }

        cp_wait<1>();
        __syncthreads();
        if (t + 1 < CT)
            ldfrag(cur, base0 + ((t + 1) % NSTAGE) * STAGE_BYTES, 0);
    }

    // epilogue
    const int gr = lane >> 2, qd = lane & 3;
    float rs[4][2];
    if (MODE == 4) {
#pragma unroll
        for (int im = 0; im < 4; im++)
#pragma unroll
            for (int h = 0; h < 2; h++)
                rs[im][h] = rowscale[bz * LQ + bm * BM + warp_m * 64 + im * 16 + gr + h * 8];
    }
#pragma unroll
    for (int im = 0; im < 4; im++) {
#pragma unroll
        for (int in = 0; in < 8; in++) {
            const long long row0 = (long long)bm * BM + warp_m * 64 + im * 16 + gr;
            const int col = bn * BN + warp_n * 64 + in * 8 + qd * 2;
#pragma unroll
            for (int h = 0; h < 2; h++) {
                const long long row = row0 + h * 8;
                const float v0 = acc[im][in][2 * h + 0];
                const float v1 = acc[im][in][2 * h + 1];
                if (MODE == 0) {
                    *(float2*)(Cf + bz * sC + row * ldc + col) = make_float2(alpha * v0, alpha * v1);
                } else if (MODE == 2) {
                    *(__half2*)(Ch + bz * sC + row * ldc + col) =
                        __halves2half2(__float2half_rn(alpha * v0), __float2half_rn(alpha * v1));
                } else if (MODE == 3) {
                    *(__half2*)(Ch + bz * sC + row * ldc + col) =
                        __halves2half2(__float2half_rn(__expf(alpha * v0)),
                                       __float2half_rn(__expf(alpha * v1)));
                } else {  // MODE 4
                    const float s = rs[im][h];
                    *(__half2*)(Ch + bz * sC + row * ldc + col) =
                        __halves2half2(__float2half_rn(s * v0), __float2half_rn(s * v1));
                }
            }
        }
    }
}

// ---- fp32 -> fp16 convert (two arrays in one launch) ----
__global__ void __launch_bounds__(256)
conv2_f16(const float4* __restrict__ s0, __half2* __restrict__ d0, int n0,
          const float4* __restrict__ s1, __half2* __restrict__ d1, int n1)
{
    const int total = n0 + n1;
    for (int i = blockIdx.x * blockDim.x + threadIdx.x; i < total; i += gridDim.x * blockDim.x) {
        const float4* s = (i < n0) ? s0 : s1;
        __half2* d = (i < n0) ? d0 : d1;
        const int j = (i < n0) ? i : i - n0;
        const float4 v = s[j];
        d[2 * j]     = __halves2half2(__float2half_rn(v.x), __float2half_rn(v.y));
        d[2 * j + 1] = __halves2half2(__float2half_rn(v.z), __float2half_rn(v.w));
    }
}

// ---- Wc [e,d] fp32 -> WcT [d,e] fp16 ----
__global__ void __launch_bounds__(256)
transpose_w(const float* __restrict__ src, __half* __restrict__ dst)
{
    __shared__ float t[32][33];
    const int tx = threadIdx.x, ty = threadIdx.y;   // (32, 8)
    const int eb = blockIdx.y, db = blockIdx.x;
#pragma unroll
    for (int r = 0; r < 4; r++)
        t[ty + r * 8][tx] = src[(long long)(eb * 32 + ty + r * 8) * DD + db * 32 + tx];
    __syncthreads();
#pragma unroll
    for (int r = 0; r < 4; r++) {
        const int drow = db * 32 + ty + r * 8;
        const int ecol = eb * 32 + tx;
        dst[(long long)drow * DD + ecol] = __float2half_rn(t[tx][ty + r * 8]);
    }
}

// ---- sum rows of E (fp16), emit attn fp32 = E*inv and rowinv (512 threads) ----
__global__ void __launch_bounds__(512)
sumscale(const __half* __restrict__ E, float* __restrict__ attn, float* __restrict__ rowinv)
{
    const long long row = blockIdx.x;
    const __half* pe = E + row * (long long)LC;
    float* pa = attn + row * (long long)LC;
    const int tid = threadIdx.x;
    const int lane = tid & 31, wid = tid >> 5;
    __shared__ float sred[16];
    __shared__ float sbcast;

    const uint2 v = ((const uint2*)pe)[tid];   // 4 halfs
    float f[4];
    {
        const __half2* hp = (const __half2*)&v;
        const float2 t0 = __half22float2(hp[0]);
        const float2 t1 = __half22float2(hp[1]);
        f[0] = t0.x; f[1] = t0.y; f[2] = t1.x; f[3] = t1.y;
    }

    float ssum = f[0] + f[1] + f[2] + f[3];
#pragma unroll
    for (int off = 16; off; off >>= 1) ssum += __shfl_xor_sync(0xffffffffu, ssum, off);
    if (lane == 0) sred[wid] = ssum;
    __syncthreads();
    if (tid == 0) {
        float t = 0.0f;
#pragma unroll
        for (int w = 0; w < 16; w++) t += sred[w];
        sbcast = 1.0f / t;
        rowinv[row] = sbcast;
    }
    __syncthreads();
    const float inv = sbcast;

    ((float4*)pa)[tid] = make_float4(f[0] * inv, f[1] * inv, f[2] * inv, f[3] * inv);
}

static void* dsym(const void* sym) { void* p = nullptr; cudaGetSymbolAddress(&p, sym); return p; }

extern "C" void kernel_launch(void* const* d_in, const int* in_sizes, int n_in,
                              void* d_out, int out_size)
{
    const float* query = (const float*)d_in[0];
    const float* bank  = (const float*)d_in[1];
    const float* Wc    = (const float*)d_in[2];
    const float* Woq   = (const float*)d_in[3];
    const float* Woc   = (const float*)d_in[4];

    float* out  = (float*)d_out;
    float* attn = out + (long long)BB * LQ * DD;

    __half* qh   = (__half*)dsym(g_qh);
    __half* bh   = (__half*)dsym(g_bh);
    __half* qwh  = (__half*)dsym(g_qwh);
    __half* eh   = (__half*)dsym(g_eh);
    __half* vh   = (__half*)dsym(g_vh);
    __half* wctT = (__half*)dsym(g_wctT);
    __half* woqh = (__half*)dsym(g_woqh);
    __half* woch = (__half*)dsym(g_woch);
    float*  rinv = (float*)dsym(g_rowinv);

    cudaFuncSetAttribute(hgemm<0,0>, cudaFuncAttributeMaxDynamicSharedMemorySize, SMEM_DYN);
    cudaFuncSetAttribute(hgemm<2,0>, cudaFuncAttributeMaxDynamicSharedMemorySize, SMEM_DYN);
    cudaFuncSetAttribute(hgemm<3,0>, cudaFuncAttributeMaxDynamicSharedMemorySize, SMEM_DYN);
    cudaFuncSetAttribute(hgemm<4,1>, cudaFuncAttributeMaxDynamicSharedMemorySize, SMEM_DYN);

    conv2_f16<<<8192, 256>>>((const float4*)query, (__half2*)qh, NQ_ELEMS / 4,
                             (const float4*)bank,  (__half2*)bh, NB_ELEMS / 4);
    conv2_f16<<<1024, 256>>>((const float4*)Woq, (__half2*)woqh, NW_ELEMS / 4,
                             (const float4*)Woc, (__half2*)woch, NW_ELEMS / 4);
    transpose_w<<<dim3(DD / 32, DD / 32), dim3(32, 8)>>>(Wc, wctT);

    // G1': qW = q @ WcT^T (NT, flat M=32768) -> fp16 qwh
    {
        GemmArgs s = { qh, wctT, nullptr, nullptr };
        hgemm<2,0><<<dim3(DD / BN, (BB * LQ) / BM, 1), 256, SMEM_DYN>>>(
            s, 1, DD, DD, nullptr, qwh, nullptr, DD, 0LL, 0LL, 0LL, 1.0f);
    }
    // G2': E = exp((1/32) qW @ bank^T) (NT, per batch) -> fp16 eh
    {
        GemmArgs s = { qwh, bh, nullptr, nullptr };
        hgemm<3,0><<<dim3(LC / BN, LQ / BM, BB), 256, SMEM_DYN>>>(
            s, 1, DD, DD, nullptr, eh, nullptr, LC,
            (long long)LQ * DD, (long long)LC * DD, (long long)LQ * LC, 0.03125f);
    }
    // sums + attn fp32 output + rowinv
    sumscale<<<BB * LQ, 512>>>(eh, attn, rinv);

    // G3: context = (E @ bank) * rowinv (NN, per batch) -> fp16 vh
    {
        GemmArgs s = { eh, bh, nullptr, nullptr };
        hgemm<4,1><<<dim3(DD / BN, LQ / BM, BB), 256, SMEM_DYN>>>(
            s, 1, LC, DD, nullptr, vh, rinv, DD,
            (long long)LQ * LC, (long long)LC * DD, (long long)LQ * DD, 1.0f);
    }
    // G4: out = context @ Woc^T + q @ Woq^T (flat M=32768, 2 segs) -> fp32
    {
        GemmArgs s = { vh, woch, qh, woqh };
        hgemm<0,0><<<dim3(DD / BN, (BB * LQ) / BM, 1), 256, SMEM_DYN>>>(
            s, 2, DD, DD, out, nullptr, nullptr, DD, 0LL, 0LL, 0LL, 1.0f);
    }
}